// round 1
// baseline (speedup 1.0000x reference)
#include <cuda_runtime.h>

#define SLEN 512
#define BB   8
#define HH   16
#define DD   1024
#define WD   64

// Scratch (device globals — no allocation allowed in kernel_launch)
__device__ float g_Q [HH*BB*SLEN*WD];   // [h][b][i][w]
__device__ float g_K [HH*BB*SLEN*WD];
__device__ float g_V [HH*BB*SLEN*WD];
__device__ float g_PK[HH*2*SLEN*WD];    // [h][r][w], r in [0,1024)
__device__ float g_PQ[HH*2*SLEN*WD];

// ---------------------------------------------------------------------------
// Projection GEMM: out[(n>>6)*M + m][n&63] = sum_k A[m][k]*W[n][k] + bias[n]
// A: [M][1024] row-major, W: [1024][1024] row-major ([n][k]).
// Tile 64x64, BK=16, 256 threads, 4x4 micro-tile per thread.
// ---------------------------------------------------------------------------
__global__ __launch_bounds__(256) void proj_kernel(
    const float* __restrict__ A, const float* __restrict__ W,
    const float* __restrict__ bias, float* __restrict__ out, int M)
{
    __shared__ float As[16*68];   // [k][m], pitch 68
    __shared__ float Ws[16*68];   // [k][n], pitch 68

    const int m0 = blockIdx.x * 64;
    const int n0 = blockIdx.y * 64;
    const int tid = threadIdx.x;
    const int ty = tid >> 4;          // 0..15 -> rows 4ty..4ty+3
    const int tx = tid & 15;          // 0..15 -> cols 4tx..4tx+3
    const int lr = tid >> 2;          // 0..63 load row
    const int lc = (tid & 3) << 2;    // 0,4,8,12 load col

    float acc[4][4] = {};

    for (int k0 = 0; k0 < DD; k0 += 16) {
        float4 av = *(const float4*)(A + (size_t)(m0 + lr)*DD + k0 + lc);
        float4 wv = *(const float4*)(W + (size_t)(n0 + lr)*DD + k0 + lc);
        __syncthreads();
        As[(lc+0)*68 + lr] = av.x; As[(lc+1)*68 + lr] = av.y;
        As[(lc+2)*68 + lr] = av.z; As[(lc+3)*68 + lr] = av.w;
        Ws[(lc+0)*68 + lr] = wv.x; Ws[(lc+1)*68 + lr] = wv.y;
        Ws[(lc+2)*68 + lr] = wv.z; Ws[(lc+3)*68 + lr] = wv.w;
        __syncthreads();
        #pragma unroll
        for (int k = 0; k < 16; k++) {
            float4 a4 = *(const float4*)(As + k*68 + 4*ty);
            float4 w4 = *(const float4*)(Ws + k*68 + 4*tx);
            float a[4] = {a4.x, a4.y, a4.z, a4.w};
            float w[4] = {w4.x, w4.y, w4.z, w4.w};
            #pragma unroll
            for (int r = 0; r < 4; r++)
                #pragma unroll
                for (int c = 0; c < 4; c++)
                    acc[r][c] += a[r] * w[c];
        }
    }

    const int hblk = n0 >> 6;   // constant across the CTA (n0 multiple of 64)
    #pragma unroll
    for (int r = 0; r < 4; r++) {
        int m = m0 + 4*ty + r;
        float4 ov;
        ov.x = acc[r][0] + bias[n0 + 4*tx + 0];
        ov.y = acc[r][1] + bias[n0 + 4*tx + 1];
        ov.z = acc[r][2] + bias[n0 + 4*tx + 2];
        ov.w = acc[r][3] + bias[n0 + 4*tx + 3];
        *(float4*)(out + ((size_t)hblk*M + m)*64 + 4*tx) = ov;
    }
}

// ---------------------------------------------------------------------------
// Fused disentangled flash attention.
// Grid: (8 i-tiles, B, H), 256 threads, 4x4 micro-tiles over a 64x64 score tile.
// s[i,j] = (q_i.k_j + q_i.pos_k[i-j+511] + k_j.pos_q[i-j+511]) * scale
// Online softmax over 8 key tiles, accumulate P@V, write (B,S,H*64) output.
// ---------------------------------------------------------------------------
#define ATTN_SMEM_FLOATS (4*64*68 + 2*64*132)
#define ATTN_SMEM_BYTES  (ATTN_SMEM_FLOATS * 4)

__global__ __launch_bounds__(256, 1) void attn_kernel(float* __restrict__ out)
{
    extern __shared__ float sm[];
    float* QsT = sm;                 // [w][i]  pitch 68 (transposed)
    float* KsT = QsT + 64*68;        // [w][j]  pitch 68 (transposed)
    float* Vs  = KsT + 64*68;        // [j][w]  pitch 68
    float* Ps  = Vs  + 64*68;        // [i][j]  pitch 68
    float* PKT = Ps  + 64*68;        // [w][d]  pitch 132 (transposed band, 128 rows)
    float* PQT = PKT + 64*132;       // [w][d]  pitch 132

    const int h  = blockIdx.z;
    const int b  = blockIdx.y;
    const int i0 = blockIdx.x * 64;
    const int tid = threadIdx.x;
    const int ty = tid >> 4;         // rows 4ty..4ty+3
    const int tx = tid & 15;         // cols 4tx..4tx+3

    const float* Qg  = g_Q  + ((size_t)(h*BB + b)*SLEN + i0)*WD;
    const float* Kg  = g_K  + (size_t)(h*BB + b)*SLEN*WD;
    const float* Vg  = g_V  + (size_t)(h*BB + b)*SLEN*WD;
    const float* PKg = g_PK + (size_t)h*2*SLEN*WD;
    const float* PQg = g_PQ + (size_t)h*2*SLEN*WD;

    // Load Q tile transposed into smem
    for (int t = tid; t < 64*16; t += 256) {
        int r = t >> 4, c4 = (t & 15) << 2;
        float4 v = *(const float4*)(Qg + r*WD + c4);
        QsT[(c4+0)*68 + r] = v.x; QsT[(c4+1)*68 + r] = v.y;
        QsT[(c4+2)*68 + r] = v.z; QsT[(c4+3)*68 + r] = v.w;
    }

    float m_i[4], l_i[4], o[4][4];
    #pragma unroll
    for (int r = 0; r < 4; r++) {
        m_i[r] = -1e30f; l_i[r] = 0.f;
        #pragma unroll
        for (int c = 0; c < 4; c++) o[r][c] = 0.f;
    }

    const float scale = rsqrtf(192.0f);   // 1/sqrt(64*3)
    const int dkb = 4*ty - 4*tx + 60;     // band base for this thread (mult of 4)

    for (int jt = 0; jt < 8; jt++) {
        const int j0 = jt * 64;
        const int r0 = i0 - j0 + 448;     // band rows r0..r0+127, always in [0,1024)
        __syncthreads();                  // prior PV / Ps use complete

        // Load K (transposed), V (row-major)
        for (int t = tid; t < 64*16; t += 256) {
            int r = t >> 4, c4 = (t & 15) << 2;
            float4 kv = *(const float4*)(Kg + (j0 + r)*WD + c4);
            KsT[(c4+0)*68 + r] = kv.x; KsT[(c4+1)*68 + r] = kv.y;
            KsT[(c4+2)*68 + r] = kv.z; KsT[(c4+3)*68 + r] = kv.w;
            float4 vv = *(const float4*)(Vg + (j0 + r)*WD + c4);
            *(float4*)(Vs + r*68 + c4) = vv;
        }
        // Load pos_k / pos_q bands (transposed)
        for (int t = tid; t < 128*16; t += 256) {
            int r = t >> 4, c4 = (t & 15) << 2;
            float4 pkv = *(const float4*)(PKg + (size_t)(r0 + r)*WD + c4);
            PKT[(c4+0)*132 + r] = pkv.x; PKT[(c4+1)*132 + r] = pkv.y;
            PKT[(c4+2)*132 + r] = pkv.z; PKT[(c4+3)*132 + r] = pkv.w;
            float4 pqv = *(const float4*)(PQg + (size_t)(r0 + r)*WD + c4);
            PQT[(c4+0)*132 + r] = pqv.x; PQT[(c4+1)*132 + r] = pqv.y;
            PQT[(c4+2)*132 + r] = pqv.z; PQT[(c4+3)*132 + r] = pqv.w;
        }
        __syncthreads();

        // Score tile: qk + c2p + p2c
        float s[4][4] = {};
        #pragma unroll 4
        for (int w = 0; w < 64; w++) {
            float4 qa4 = *(const float4*)(QsT + w*68 + 4*ty);
            float4 ka4 = *(const float4*)(KsT + w*68 + 4*tx);
            float4 pk0 = *(const float4*)(PKT + w*132 + dkb);
            float4 pk1 = *(const float4*)(PKT + w*132 + dkb + 4);
            float4 pq0 = *(const float4*)(PQT + w*132 + dkb);
            float4 pq1 = *(const float4*)(PQT + w*132 + dkb + 4);
            float q[4]  = {qa4.x, qa4.y, qa4.z, qa4.w};
            float k[4]  = {ka4.x, ka4.y, ka4.z, ka4.w};
            float pk[8] = {pk0.x, pk0.y, pk0.z, pk0.w, pk1.x, pk1.y, pk1.z, pk1.w};
            float pq[8] = {pq0.x, pq0.y, pq0.z, pq0.w, pq1.x, pq1.y, pq1.z, pq1.w};
            #pragma unroll
            for (int ri = 0; ri < 4; ri++)
                #pragma unroll
                for (int rj = 0; rj < 4; rj++) {
                    const int d = ri - rj + 3;   // constant after unroll
                    s[ri][rj] += q[ri]*k[rj] + q[ri]*pk[d] + k[rj]*pq[d];
                }
        }
        #pragma unroll
        for (int ri = 0; ri < 4; ri++)
            #pragma unroll
            for (int rj = 0; rj < 4; rj++)
                s[ri][rj] *= scale;

        // Online softmax update (rows owned by the 16 tx-lanes sharing ty)
        #pragma unroll
        for (int ri = 0; ri < 4; ri++) {
            float mx = fmaxf(fmaxf(s[ri][0], s[ri][1]), fmaxf(s[ri][2], s[ri][3]));
            #pragma unroll
            for (int off = 8; off > 0; off >>= 1)
                mx = fmaxf(mx, __shfl_xor_sync(0xffffffffu, mx, off));
            float mnew = fmaxf(m_i[ri], mx);
            float corr = __expf(m_i[ri] - mnew);
            float p0 = __expf(s[ri][0] - mnew);
            float p1 = __expf(s[ri][1] - mnew);
            float p2 = __expf(s[ri][2] - mnew);
            float p3 = __expf(s[ri][3] - mnew);
            float rs = p0 + p1 + p2 + p3;
            #pragma unroll
            for (int off = 8; off > 0; off >>= 1)
                rs += __shfl_xor_sync(0xffffffffu, rs, off);
            l_i[ri] = l_i[ri]*corr + rs;
            m_i[ri] = mnew;
            #pragma unroll
            for (int rw = 0; rw < 4; rw++) o[ri][rw] *= corr;
            float* prow = Ps + (4*ty + ri)*68 + 4*tx;
            prow[0] = p0; prow[1] = p1; prow[2] = p2; prow[3] = p3;
        }
        __syncthreads();

        // O += P @ V
        #pragma unroll 4
        for (int j = 0; j < 64; j++) {
            float4 vv = *(const float4*)(Vs + j*68 + 4*tx);
            float va[4] = {vv.x, vv.y, vv.z, vv.w};
            float pa[4];
            #pragma unroll
            for (int ri = 0; ri < 4; ri++) pa[ri] = Ps[(4*ty + ri)*68 + j];
            #pragma unroll
            for (int ri = 0; ri < 4; ri++)
                #pragma unroll
                for (int rw = 0; rw < 4; rw++)
                    o[ri][rw] += pa[ri] * va[rw];
        }
    }

    // Write output: out[b][i][h*64 + w]
    #pragma unroll
    for (int ri = 0; ri < 4; ri++) {
        int i = i0 + 4*ty + ri;
        float inv = 1.0f / l_i[ri];
        float4 ov = { o[ri][0]*inv, o[ri][1]*inv, o[ri][2]*inv, o[ri][3]*inv };
        *(float4*)(out + ((size_t)b*SLEN + i)*DD + h*64 + 4*tx) = ov;
    }
}

// ---------------------------------------------------------------------------
// Launch
// ---------------------------------------------------------------------------
extern "C" void kernel_launch(void* const* d_in, const int* in_sizes, int n_in,
                              void* d_out, int out_size)
{
    (void)in_sizes; (void)n_in; (void)out_size;
    const float* x  = (const float*)d_in[0];
    const float* re = (const float*)d_in[1];   // rel_embeddings: full 1024 rows used
    const float* Wq = (const float*)d_in[2];
    const float* bq = (const float*)d_in[3];
    const float* Wk = (const float*)d_in[4];
    const float* bk = (const float*)d_in[5];
    const float* Wv = (const float*)d_in[6];
    const float* bv = (const float*)d_in[7];
    // d_in[8] = relative_pos (deterministic i-j, computed analytically)
    // d_in[9] = mask (all true -> no-op)
    float* out = (float*)d_out;

    void *qp, *kp, *vp, *pkp, *pqp;
    cudaGetSymbolAddress(&qp,  g_Q);
    cudaGetSymbolAddress(&kp,  g_K);
    cudaGetSymbolAddress(&vp,  g_V);
    cudaGetSymbolAddress(&pkp, g_PK);
    cudaGetSymbolAddress(&pqp, g_PQ);

    cudaFuncSetAttribute(attn_kernel, cudaFuncAttributeMaxDynamicSharedMemorySize,
                         ATTN_SMEM_BYTES);

    dim3 blk(256);
    proj_kernel<<<dim3(64, 16), blk>>>(x,  Wq, bq, (float*)qp,  BB*SLEN);
    proj_kernel<<<dim3(64, 16), blk>>>(x,  Wk, bk, (float*)kp,  BB*SLEN);
    proj_kernel<<<dim3(64, 16), blk>>>(x,  Wv, bv, (float*)vp,  BB*SLEN);
    proj_kernel<<<dim3(16, 16), blk>>>(re, Wk, bk, (float*)pkp, 2*SLEN);
    proj_kernel<<<dim3(16, 16), blk>>>(re, Wq, bq, (float*)pqp, 2*SLEN);

    attn_kernel<<<dim3(8, BB, HH), blk, ATTN_SMEM_BYTES>>>(out);
}

// round 2
// speedup vs baseline: 1.0439x; 1.0439x over previous
#include <cuda_runtime.h>

#define SLEN 512
#define BB   8
#define HH   16
#define DD   1024
#define WD   64

// Scratch (device globals — no allocation allowed in kernel_launch)
__device__ float g_Q [HH*BB*SLEN*WD];   // [h][b][i][w]
__device__ float g_K [HH*BB*SLEN*WD];
__device__ float g_V [HH*BB*SLEN*WD];
__device__ float g_PK[HH*2*SLEN*WD];    // [h][r][w], r in [0,1024)
__device__ float g_PQ[HH*2*SLEN*WD];

// ---------------------------------------------------------------------------
// Projection GEMM v2: out[(n>>6)*M + m][n&63] = sum_k A[m][k]*W[n][k] + bias[n]
// 128x128 tile, BK=16, 256 threads, 8x8 micro-tile. 0.25 smem floats per FMA.
// ---------------------------------------------------------------------------
__global__ __launch_bounds__(256, 2) void proj_kernel(
    const float* __restrict__ A, const float* __restrict__ W,
    const float* __restrict__ bias, float* __restrict__ out, int M)
{
    __shared__ float As[16*132];   // [k][m], pitch 132
    __shared__ float Ws[16*132];   // [k][n], pitch 132

    const int m0 = blockIdx.x * 128;
    const int n0 = blockIdx.y * 128;
    const int tid = threadIdx.x;
    const int ty = tid >> 4;          // 0..15 -> rows 8ty..8ty+7
    const int tx = tid & 15;          // 0..15 -> cols 8tx..8tx+7
    const int lr = tid >> 2;          // 0..63 load row (and +64)
    const int lc = (tid & 3) << 2;    // 0,4,8,12 load col

    float acc[8][8] = {};

    for (int k0 = 0; k0 < DD; k0 += 16) {
        float4 a0 = *(const float4*)(A + (size_t)(m0 + lr     )*DD + k0 + lc);
        float4 a1 = *(const float4*)(A + (size_t)(m0 + lr + 64)*DD + k0 + lc);
        float4 w0 = *(const float4*)(W + (size_t)(n0 + lr     )*DD + k0 + lc);
        float4 w1 = *(const float4*)(W + (size_t)(n0 + lr + 64)*DD + k0 + lc);
        __syncthreads();
        As[(lc+0)*132 + lr] = a0.x; As[(lc+1)*132 + lr] = a0.y;
        As[(lc+2)*132 + lr] = a0.z; As[(lc+3)*132 + lr] = a0.w;
        As[(lc+0)*132 + lr+64] = a1.x; As[(lc+1)*132 + lr+64] = a1.y;
        As[(lc+2)*132 + lr+64] = a1.z; As[(lc+3)*132 + lr+64] = a1.w;
        Ws[(lc+0)*132 + lr] = w0.x; Ws[(lc+1)*132 + lr] = w0.y;
        Ws[(lc+2)*132 + lr] = w0.z; Ws[(lc+3)*132 + lr] = w0.w;
        Ws[(lc+0)*132 + lr+64] = w1.x; Ws[(lc+1)*132 + lr+64] = w1.y;
        Ws[(lc+2)*132 + lr+64] = w1.z; Ws[(lc+3)*132 + lr+64] = w1.w;
        __syncthreads();
        #pragma unroll
        for (int k = 0; k < 16; k++) {
            float4 aa0 = *(const float4*)(As + k*132 + 8*ty);
            float4 aa1 = *(const float4*)(As + k*132 + 8*ty + 4);
            float4 bb0 = *(const float4*)(Ws + k*132 + 8*tx);
            float4 bb1 = *(const float4*)(Ws + k*132 + 8*tx + 4);
            float a[8] = {aa0.x, aa0.y, aa0.z, aa0.w, aa1.x, aa1.y, aa1.z, aa1.w};
            float b[8] = {bb0.x, bb0.y, bb0.z, bb0.w, bb1.x, bb1.y, bb1.z, bb1.w};
            #pragma unroll
            for (int r = 0; r < 8; r++)
                #pragma unroll
                for (int c = 0; c < 8; c++)
                    acc[r][c] += a[r] * b[c];
        }
    }

    // Epilogue: bias add + head-major store
    #pragma unroll
    for (int r = 0; r < 8; r++) {
        int m = m0 + 8*ty + r;
        #pragma unroll
        for (int cb = 0; cb < 2; cb++) {
            int n = n0 + 8*tx + 4*cb;
            int hblk = n >> 6;
            int nin  = n & 63;
            float4 ov;
            ov.x = acc[r][4*cb+0] + bias[n+0];
            ov.y = acc[r][4*cb+1] + bias[n+1];
            ov.z = acc[r][4*cb+2] + bias[n+2];
            ov.w = acc[r][4*cb+3] + bias[n+3];
            *(float4*)(out + ((size_t)hblk*M + m)*64 + nin) = ov;
        }
    }
}

// ---------------------------------------------------------------------------
// Fused disentangled flash attention v2.
// Bi=128, Bj=64, 512 threads (16 warps), 4x4 micro-tiles.
// s[i,j] = (q_i.k_j + q_i.pos_k[i-j+511] + k_j.pos_q[i-j+511]) * scale
// ---------------------------------------------------------------------------
// smem floats: QsT 64*128 + KsT 64*64 + Vs 64*64 + PKT 64*192 + PQT 64*192
#define OFF_QST 0
#define OFF_KST (64*128)
#define OFF_VS  (OFF_KST + 64*64)
#define OFF_PKT (OFF_VS + 64*64)
#define OFF_PQT (OFF_PKT + 64*192)
#define ATTN_SMEM_FLOATS (OFF_PQT + 64*192)
#define ATTN_SMEM_BYTES  (ATTN_SMEM_FLOATS * 4)   // 163840 B

__global__ __launch_bounds__(512, 1) void attn_kernel(float* __restrict__ out)
{
    extern __shared__ float sm[];
    float* QsT = sm + OFF_QST;     // [w][i]  pitch 128
    float* KsT = sm + OFF_KST;     // [w][j]  pitch 64
    float* Vs  = sm + OFF_VS;      // [j][w]  pitch 64
    float* PKT = sm + OFF_PKT;     // [w][a]  pitch 192
    float* PQT = sm + OFF_PQT;     // [w][a]  pitch 192
    float* Ps  = sm + OFF_PKT;     // [i][j]  pitch 68 (ALIASED over PKT)

    const int h  = blockIdx.z;
    const int b  = blockIdx.y;
    const int i0 = blockIdx.x * 128;
    const int tid = threadIdx.x;
    const int ty = tid >> 4;         // 0..31 -> rows 4ty..4ty+3
    const int tx = tid & 15;         // 0..15 -> cols 4tx..4tx+3

    const float* Qg  = g_Q  + ((size_t)(h*BB + b)*SLEN + i0)*WD;
    const float* Kg  = g_K  + (size_t)(h*BB + b)*SLEN*WD;
    const float* Vg  = g_V  + (size_t)(h*BB + b)*SLEN*WD;
    const float* PKg = g_PK + (size_t)h*2*SLEN*WD;
    const float* PQg = g_PQ + (size_t)h*2*SLEN*WD;

    // Stage Q transposed: consecutive lanes -> consecutive rows => conflict-free STS
    for (int t = tid; t < 128*16; t += 512) {
        int r = t & 127, c4 = (t >> 7) << 2;
        float4 v = *(const float4*)(Qg + r*WD + c4);
        QsT[(c4+0)*128 + r] = v.x; QsT[(c4+1)*128 + r] = v.y;
        QsT[(c4+2)*128 + r] = v.z; QsT[(c4+3)*128 + r] = v.w;
    }

    float m_i[4], l_i[4], o[4][4];
    #pragma unroll
    for (int r = 0; r < 4; r++) {
        m_i[r] = -1e30f; l_i[r] = 0.f;
        #pragma unroll
        for (int c = 0; c < 4; c++) o[r][c] = 0.f;
    }

    const float scale = rsqrtf(192.0f);   // 1/sqrt(64*3)
    const int dkb = 4*ty - 4*tx + 60;     // aligned band window base (mult of 4)

    for (int jt = 0; jt < 8; jt++) {
        const int j0 = jt * 64;
        const int r0 = i0 - j0 + 448;     // abs band start; rows r0..r0+191 in [0,1024)
        __syncthreads();                  // prior PV reads of Vs/Ps complete

        // K transposed (conflict-free stores), V row-major (coalesced)
        for (int t = tid; t < 64*16; t += 512) {
            int r = t & 63, c4 = (t >> 6) << 2;
            float4 kv = *(const float4*)(Kg + (j0 + r)*WD + c4);
            KsT[(c4+0)*64 + r] = kv.x; KsT[(c4+1)*64 + r] = kv.y;
            KsT[(c4+2)*64 + r] = kv.z; KsT[(c4+3)*64 + r] = kv.w;
        }
        for (int t = tid; t < 64*16; t += 512) {
            int r = t >> 4, c4 = (t & 15) << 2;
            *(float4*)(Vs + r*64 + c4) = *(const float4*)(Vg + (j0 + r)*WD + c4);
        }
        // Bands transposed: 192 rows each
        for (int t = tid; t < 192*16; t += 512) {
            int g = t / 192, a = t - g*192, c4 = g << 2;
            float4 pkv = *(const float4*)(PKg + (size_t)(r0 + a)*WD + c4);
            PKT[(c4+0)*192 + a] = pkv.x; PKT[(c4+1)*192 + a] = pkv.y;
            PKT[(c4+2)*192 + a] = pkv.z; PKT[(c4+3)*192 + a] = pkv.w;
            float4 pqv = *(const float4*)(PQg + (size_t)(r0 + a)*WD + c4);
            PQT[(c4+0)*192 + a] = pqv.x; PQT[(c4+1)*192 + a] = pqv.y;
            PQT[(c4+2)*192 + a] = pqv.z; PQT[(c4+3)*192 + a] = pqv.w;
        }
        __syncthreads();

        // Score tile: qk + c2p + p2c
        float s[4][4] = {};
        #pragma unroll 4
        for (int w = 0; w < 64; w++) {
            float4 qa4 = *(const float4*)(QsT + w*128 + 4*ty);
            float4 ka4 = *(const float4*)(KsT + w*64  + 4*tx);
            float4 pk0 = *(const float4*)(PKT + w*192 + dkb);
            float4 pk1 = *(const float4*)(PKT + w*192 + dkb + 4);
            float4 pq0 = *(const float4*)(PQT + w*192 + dkb);
            float4 pq1 = *(const float4*)(PQT + w*192 + dkb + 4);
            float q[4]  = {qa4.x, qa4.y, qa4.z, qa4.w};
            float k[4]  = {ka4.x, ka4.y, ka4.z, ka4.w};
            float pk[8] = {pk0.x, pk0.y, pk0.z, pk0.w, pk1.x, pk1.y, pk1.z, pk1.w};
            float pq[8] = {pq0.x, pq0.y, pq0.z, pq0.w, pq1.x, pq1.y, pq1.z, pq1.w};
            #pragma unroll
            for (int ri = 0; ri < 4; ri++)
                #pragma unroll
                for (int rj = 0; rj < 4; rj++) {
                    const int d = ri - rj + 3;   // constant after unroll
                    s[ri][rj] += q[ri]*k[rj] + q[ri]*pk[d] + k[rj]*pq[d];
                }
        }
        #pragma unroll
        for (int ri = 0; ri < 4; ri++)
            #pragma unroll
            for (int rj = 0; rj < 4; rj++)
                s[ri][rj] *= scale;

        __syncthreads();   // band reads done before Ps (aliased) is written

        // Online softmax update (row shared by 16 tx lanes of same ty = half warp)
        #pragma unroll
        for (int ri = 0; ri < 4; ri++) {
            float mx = fmaxf(fmaxf(s[ri][0], s[ri][1]), fmaxf(s[ri][2], s[ri][3]));
            #pragma unroll
            for (int off = 8; off > 0; off >>= 1)
                mx = fmaxf(mx, __shfl_xor_sync(0xffffffffu, mx, off));
            float mnew = fmaxf(m_i[ri], mx);
            float corr = __expf(m_i[ri] - mnew);
            float p0 = __expf(s[ri][0] - mnew);
            float p1 = __expf(s[ri][1] - mnew);
            float p2 = __expf(s[ri][2] - mnew);
            float p3 = __expf(s[ri][3] - mnew);
            float rs = p0 + p1 + p2 + p3;
            #pragma unroll
            for (int off = 8; off > 0; off >>= 1)
                rs += __shfl_xor_sync(0xffffffffu, rs, off);
            l_i[ri] = l_i[ri]*corr + rs;
            m_i[ri] = mnew;
            #pragma unroll
            for (int rw = 0; rw < 4; rw++) o[ri][rw] *= corr;
            float4 pv = {p0, p1, p2, p3};
            *(float4*)(Ps + (4*ty + ri)*68 + 4*tx) = pv;
        }
        __syncthreads();

        // O += P @ V
        #pragma unroll 4
        for (int j = 0; j < 64; j++) {
            float4 vv = *(const float4*)(Vs + j*64 + 4*tx);
            float va[4] = {vv.x, vv.y, vv.z, vv.w};
            float pa[4];
            #pragma unroll
            for (int ri = 0; ri < 4; ri++) pa[ri] = Ps[(4*ty + ri)*68 + j];
            #pragma unroll
            for (int ri = 0; ri < 4; ri++)
                #pragma unroll
                for (int rw = 0; rw < 4; rw++)
                    o[ri][rw] += pa[ri] * va[rw];
        }
    }

    // Write output: out[b][i][h*64 + w]
    #pragma unroll
    for (int ri = 0; ri < 4; ri++) {
        int i = i0 + 4*ty + ri;
        float inv = 1.0f / l_i[ri];
        float4 ov = { o[ri][0]*inv, o[ri][1]*inv, o[ri][2]*inv, o[ri][3]*inv };
        *(float4*)(out + ((size_t)b*SLEN + i)*DD + h*64 + 4*tx) = ov;
    }
}

// ---------------------------------------------------------------------------
// Launch
// ---------------------------------------------------------------------------
extern "C" void kernel_launch(void* const* d_in, const int* in_sizes, int n_in,
                              void* d_out, int out_size)
{
    (void)in_sizes; (void)n_in; (void)out_size;
    const float* x  = (const float*)d_in[0];
    const float* re = (const float*)d_in[1];
    const float* Wq = (const float*)d_in[2];
    const float* bq = (const float*)d_in[3];
    const float* Wk = (const float*)d_in[4];
    const float* bk = (const float*)d_in[5];
    const float* Wv = (const float*)d_in[6];
    const float* bv = (const float*)d_in[7];
    float* out = (float*)d_out;

    void *qp, *kp, *vp, *pkp, *pqp;
    cudaGetSymbolAddress(&qp,  g_Q);
    cudaGetSymbolAddress(&kp,  g_K);
    cudaGetSymbolAddress(&vp,  g_V);
    cudaGetSymbolAddress(&pkp, g_PK);
    cudaGetSymbolAddress(&pqp, g_PQ);

    cudaFuncSetAttribute(attn_kernel, cudaFuncAttributeMaxDynamicSharedMemorySize,
                         ATTN_SMEM_BYTES);

    dim3 blk(256);
    proj_kernel<<<dim3(32, 8), blk>>>(x,  Wq, bq, (float*)qp,  BB*SLEN);
    proj_kernel<<<dim3(32, 8), blk>>>(x,  Wk, bk, (float*)kp,  BB*SLEN);
    proj_kernel<<<dim3(32, 8), blk>>>(x,  Wv, bv, (float*)vp,  BB*SLEN);
    proj_kernel<<<dim3( 8, 8), blk>>>(re, Wk, bk, (float*)pkp, 2*SLEN);
    proj_kernel<<<dim3( 8, 8), blk>>>(re, Wq, bq, (float*)pqp, 2*SLEN);

    attn_kernel<<<dim3(4, BB, HH), dim3(512), ATTN_SMEM_BYTES>>>(out);
}

// round 4
// speedup vs baseline: 1.6193x; 1.5512x over previous
#include <cuda_runtime.h>
#include <cuda_bf16.h>
#include <cstdint>

#define SLEN 512
#define BB   8
#define HH   16
#define DD   1024
#define WD   64

// Scratch (device globals — no allocation allowed in kernel_launch)
__device__ float g_Q [HH*BB*SLEN*WD];   // [h][b][i][w]
__device__ float g_K [HH*BB*SLEN*WD];
__device__ float g_V [HH*BB*SLEN*WD];
__device__ float g_PK[HH*2*SLEN*WD];    // [h][r][w]
__device__ float g_PQ[HH*2*SLEN*WD];

// ===========================================================================
// mma.sync bf16 helper (sm_80+, compiles for plain sm_100)
// ===========================================================================
__device__ __forceinline__ void mma_bf16(float* d,
    uint32_t a0, uint32_t a1, uint32_t a2, uint32_t a3,
    uint32_t b0, uint32_t b1)
{
    asm volatile(
        "mma.sync.aligned.m16n8k16.row.col.f32.bf16.bf16.f32 "
        "{%0,%1,%2,%3}, {%4,%5,%6,%7}, {%8,%9}, {%0,%1,%2,%3};"
        : "+f"(d[0]), "+f"(d[1]), "+f"(d[2]), "+f"(d[3])
        : "r"(a0), "r"(a1), "r"(a2), "r"(a3), "r"(b0), "r"(b1));
}

__device__ __forceinline__ uint32_t pack_bf16(float a, float b) {
    __nv_bfloat162 h = __floats2bfloat162_rn(a, b);
    return *reinterpret_cast<uint32_t*>(&h);
}
__device__ __forceinline__ float bf16_hi(float a) {
    return __bfloat162float(__float2bfloat16_rn(a));
}

// ===========================================================================
// Fused projection GEMM (mma.sync bf16, split hi/lo, 3 products):
//   C[5120,3072] = [x(4096); re(1024)] @ [Wq|Wk|Wv]^T  (+bias), scatter store.
// 128x128 tile, 256 threads (2x4 warps, 64x32 each), BK=32, double buffer.
// smem pitch 40 bf16 (20 words) -> fragment loads are 32-bank conflict-free.
// ===========================================================================
#define P_PITCH 20                       // words per row (40 bf16)
#define P_ARR   (128*P_PITCH)            // 2560 words per matrix array
#define P_SMEM_WORDS (2*4*P_ARR)         // 2 buffers x {A_hi,A_lo,W_hi,W_lo}
#define P_SMEM_BYTES (P_SMEM_WORDS*4)    // 81920

__global__ __launch_bounds__(256, 1) void proj_mma_kernel(
    const float* __restrict__ x, const float* __restrict__ re,
    const float* __restrict__ Wq, const float* __restrict__ bq,
    const float* __restrict__ Wk, const float* __restrict__ bk,
    const float* __restrict__ Wv, const float* __restrict__ bv,
    float* __restrict__ outQ, float* __restrict__ outK, float* __restrict__ outV,
    float* __restrict__ outPK, float* __restrict__ outPQ)
{
    extern __shared__ uint32_t smw[];
    const int m0 = blockIdx.x * 128;          // [0, 5120)
    const int n0 = blockIdx.y * 128;          // [0, 3072)
    const bool isRe = (m0 >= 4096);
    const int nreg = n0 >> 10;
    if (isRe && nreg == 2) return;            // re x Wv unused

    const int tid  = threadIdx.x;
    const int lane = tid & 31;
    const int wid  = tid >> 5;
    const int wm   = wid >> 2;                // 0..1
    const int wn   = wid & 3;                 // 0..3

    const float* Ag = isRe ? (re + (size_t)(m0 - 4096) * DD) : (x + (size_t)m0 * DD);
    const float* Wg = ((nreg == 0) ? Wq : (nreg == 1) ? Wk : Wv) + (size_t)(n0 & 1023) * DD;

    // staging row/col for this thread (4 float4 per matrix per chunk)
    const int srow[4] = { tid >> 3, (tid + 256) >> 3, (tid + 512) >> 3, (tid + 768) >> 3 };
    const int sf4  = tid & 7;                 // float4 index within 32-wide row

    float acc[4][4][4] = {};
    float4 sa[4], sw4[4];

    // --- stage chunk 0 ---
    #pragma unroll
    for (int j = 0; j < 4; j++) {
        sa[j]  = *(const float4*)(Ag + (size_t)srow[j]*DD + sf4*4);
        sw4[j] = *(const float4*)(Wg + (size_t)srow[j]*DD + sf4*4);
    }
    {
        uint32_t* Ah = smw;             uint32_t* Al = smw + P_ARR;
        uint32_t* Wh = smw + 2*P_ARR;   uint32_t* Wl = smw + 3*P_ARR;
        #pragma unroll
        for (int j = 0; j < 4; j++) {
            int wbase = srow[j]*P_PITCH + sf4*2;
            float4 v = sa[j];
            Ah[wbase]   = pack_bf16(v.x, v.y);
            Ah[wbase+1] = pack_bf16(v.z, v.w);
            Al[wbase]   = pack_bf16(v.x - bf16_hi(v.x), v.y - bf16_hi(v.y));
            Al[wbase+1] = pack_bf16(v.z - bf16_hi(v.z), v.w - bf16_hi(v.w));
            v = sw4[j];
            Wh[wbase]   = pack_bf16(v.x, v.y);
            Wh[wbase+1] = pack_bf16(v.z, v.w);
            Wl[wbase]   = pack_bf16(v.x - bf16_hi(v.x), v.y - bf16_hi(v.y));
            Wl[wbase+1] = pack_bf16(v.z - bf16_hi(v.z), v.w - bf16_hi(v.w));
        }
    }
    __syncthreads();

    for (int c = 0; c < 32; c++) {
        const int buf = c & 1;
        // issue next chunk's global loads (latency hidden behind MMA)
        if (c + 1 < 32) {
            const int kc = (c + 1) * 32;
            #pragma unroll
            for (int j = 0; j < 4; j++) {
                sa[j]  = *(const float4*)(Ag + (size_t)srow[j]*DD + kc + sf4*4);
                sw4[j] = *(const float4*)(Wg + (size_t)srow[j]*DD + kc + sf4*4);
            }
        }

        // --- MMA on current buffer ---
        {
            const uint32_t* Ah = smw + (buf*4 + 0)*P_ARR;
            const uint32_t* Al = smw + (buf*4 + 1)*P_ARR;
            const uint32_t* Wh = smw + (buf*4 + 2)*P_ARR;
            const uint32_t* Wl = smw + (buf*4 + 3)*P_ARR;
            #pragma unroll
            for (int ks = 0; ks < 2; ks++) {
                const int kw = (lane & 3) + ks*8;
                uint32_t ah[4][4], al[4][4];
                #pragma unroll
                for (int mt = 0; mt < 4; mt++) {
                    int r = wm*64 + mt*16 + (lane >> 2);
                    int b0 = r*P_PITCH + kw;
                    ah[mt][0] = Ah[b0];       ah[mt][1] = Ah[b0 + 8*P_PITCH];
                    ah[mt][2] = Ah[b0 + 4];   ah[mt][3] = Ah[b0 + 8*P_PITCH + 4];
                    al[mt][0] = Al[b0];       al[mt][1] = Al[b0 + 8*P_PITCH];
                    al[mt][2] = Al[b0 + 4];   al[mt][3] = Al[b0 + 8*P_PITCH + 4];
                }
                uint32_t bh[4][2], bl[4][2];
                #pragma unroll
                for (int nt = 0; nt < 4; nt++) {
                    int rn = wn*32 + nt*8 + (lane >> 2);
                    int b0 = rn*P_PITCH + kw;
                    bh[nt][0] = Wh[b0]; bh[nt][1] = Wh[b0 + 4];
                    bl[nt][0] = Wl[b0]; bl[nt][1] = Wl[b0 + 4];
                }
                #pragma unroll
                for (int mt = 0; mt < 4; mt++)
                    #pragma unroll
                    for (int nt = 0; nt < 4; nt++) {
                        mma_bf16(acc[mt][nt], ah[mt][0], ah[mt][1], ah[mt][2], ah[mt][3],
                                 bh[nt][0], bh[nt][1]);
                        mma_bf16(acc[mt][nt], ah[mt][0], ah[mt][1], ah[mt][2], ah[mt][3],
                                 bl[nt][0], bl[nt][1]);
                        mma_bf16(acc[mt][nt], al[mt][0], al[mt][1], al[mt][2], al[mt][3],
                                 bh[nt][0], bh[nt][1]);
                    }
            }
        }

        // --- convert+store next chunk into the other buffer ---
        if (c + 1 < 32) {
            const int ob = 1 - buf;
            uint32_t* Ah = smw + (ob*4 + 0)*P_ARR;
            uint32_t* Al = smw + (ob*4 + 1)*P_ARR;
            uint32_t* Wh = smw + (ob*4 + 2)*P_ARR;
            uint32_t* Wl = smw + (ob*4 + 3)*P_ARR;
            #pragma unroll
            for (int j = 0; j < 4; j++) {
                int wbase = srow[j]*P_PITCH + sf4*2;
                float4 v = sa[j];
                Ah[wbase]   = pack_bf16(v.x, v.y);
                Ah[wbase+1] = pack_bf16(v.z, v.w);
                Al[wbase]   = pack_bf16(v.x - bf16_hi(v.x), v.y - bf16_hi(v.y));
                Al[wbase+1] = pack_bf16(v.z - bf16_hi(v.z), v.w - bf16_hi(v.w));
                v = sw4[j];
                Wh[wbase]   = pack_bf16(v.x, v.y);
                Wh[wbase+1] = pack_bf16(v.z, v.w);
                Wl[wbase]   = pack_bf16(v.x - bf16_hi(v.x), v.y - bf16_hi(v.y));
                Wl[wbase+1] = pack_bf16(v.z - bf16_hi(v.z), v.w - bf16_hi(v.w));
            }
        }
        __syncthreads();
    }

    // --- epilogue: bias add + scattered head-major store ---
    const float* bp = (nreg == 0) ? bq : (nreg == 1) ? bk : bv;
    float* baseO;
    int Mrows, moff;
    if (!isRe) {
        baseO = (nreg == 0) ? outQ : (nreg == 1) ? outK : outV;
        Mrows = 4096; moff = m0;
    } else {
        baseO = (nreg == 0) ? outPQ : outPK;   // nreg==2 returned earlier
        Mrows = 1024; moff = m0 - 4096;
    }

    #pragma unroll
    for (int mt = 0; mt < 4; mt++) {
        int m = moff + wm*64 + mt*16 + (lane >> 2);
        #pragma unroll
        for (int nt = 0; nt < 4; nt++) {
            int ncl = (n0 & 1023) + wn*32 + nt*8 + (lane & 3)*2;
            int hh = ncl >> 6, w = ncl & 63;
            float bx = bp[ncl], by = bp[ncl + 1];
            float* d0 = baseO + ((size_t)hh*Mrows + m)*64 + w;
            float2 v0 = { acc[mt][nt][0] + bx, acc[mt][nt][1] + by };
            float2 v1 = { acc[mt][nt][2] + bx, acc[mt][nt][3] + by };
            *(float2*)d0 = v0;
            *(float2*)(d0 + 8*64) = v1;
        }
    }
}

// ===========================================================================
// Fused disentangled flash attention (round-2 version, known good)
// ===========================================================================
#define OFF_QST 0
#define OFF_KST (64*128)
#define OFF_VS  (OFF_KST + 64*64)
#define OFF_PKT (OFF_VS + 64*64)
#define OFF_PQT (OFF_PKT + 64*192)
#define ATTN_SMEM_FLOATS (OFF_PQT + 64*192)
#define ATTN_SMEM_BYTES  (ATTN_SMEM_FLOATS * 4)   // 163840 B

__global__ __launch_bounds__(512, 1) void attn_kernel(float* __restrict__ out)
{
    extern __shared__ float sm[];
    float* QsT = sm + OFF_QST;     // [w][i]  pitch 128
    float* KsT = sm + OFF_KST;     // [w][j]  pitch 64
    float* Vs  = sm + OFF_VS;      // [j][w]  pitch 64
    float* PKT = sm + OFF_PKT;     // [w][a]  pitch 192
    float* PQT = sm + OFF_PQT;     // [w][a]  pitch 192
    float* Ps  = sm + OFF_PKT;     // [i][j]  pitch 68 (ALIASED over PKT)

    const int h  = blockIdx.z;
    const int b  = blockIdx.y;
    const int i0 = blockIdx.x * 128;
    const int tid = threadIdx.x;
    const int ty = tid >> 4;
    const int tx = tid & 15;

    const float* Qg  = g_Q  + ((size_t)(h*BB + b)*SLEN + i0)*WD;
    const float* Kg  = g_K  + (size_t)(h*BB + b)*SLEN*WD;
    const float* Vg  = g_V  + (size_t)(h*BB + b)*SLEN*WD;
    const float* PKg = g_PK + (size_t)h*2*SLEN*WD;
    const float* PQg = g_PQ + (size_t)h*2*SLEN*WD;

    for (int t = tid; t < 128*16; t += 512) {
        int r = t & 127, c4 = (t >> 7) << 2;
        float4 v = *(const float4*)(Qg + r*WD + c4);
        QsT[(c4+0)*128 + r] = v.x; QsT[(c4+1)*128 + r] = v.y;
        QsT[(c4+2)*128 + r] = v.z; QsT[(c4+3)*128 + r] = v.w;
    }

    float m_i[4], l_i[4], o[4][4];
    #pragma unroll
    for (int r = 0; r < 4; r++) {
        m_i[r] = -1e30f; l_i[r] = 0.f;
        #pragma unroll
        for (int c = 0; c < 4; c++) o[r][c] = 0.f;
    }

    const float scale = rsqrtf(192.0f);
    const int dkb = 4*ty - 4*tx + 60;

    for (int jt = 0; jt < 8; jt++) {
        const int j0 = jt * 64;
        const int r0 = i0 - j0 + 448;
        __syncthreads();

        for (int t = tid; t < 64*16; t += 512) {
            int r = t & 63, c4 = (t >> 6) << 2;
            float4 kv = *(const float4*)(Kg + (j0 + r)*WD + c4);
            KsT[(c4+0)*64 + r] = kv.x; KsT[(c4+1)*64 + r] = kv.y;
            KsT[(c4+2)*64 + r] = kv.z; KsT[(c4+3)*64 + r] = kv.w;
        }
        for (int t = tid; t < 64*16; t += 512) {
            int r = t >> 4, c4 = (t & 15) << 2;
            *(float4*)(Vs + r*64 + c4) = *(const float4*)(Vg + (j0 + r)*WD + c4);
        }
        for (int t = tid; t < 192*16; t += 512) {
            int g = t / 192, a = t - g*192, c4 = g << 2;
            float4 pkv = *(const float4*)(PKg + (size_t)(r0 + a)*WD + c4);
            PKT[(c4+0)*192 + a] = pkv.x; PKT[(c4+1)*192 + a] = pkv.y;
            PKT[(c4+2)*192 + a] = pkv.z; PKT[(c4+3)*192 + a] = pkv.w;
            float4 pqv = *(const float4*)(PQg + (size_t)(r0 + a)*WD + c4);
            PQT[(c4+0)*192 + a] = pqv.x; PQT[(c4+1)*192 + a] = pqv.y;
            PQT[(c4+2)*192 + a] = pqv.z; PQT[(c4+3)*192 + a] = pqv.w;
        }
        __syncthreads();

        float s[4][4] = {};
        #pragma unroll 4
        for (int w = 0; w < 64; w++) {
            float4 qa4 = *(const float4*)(QsT + w*128 + 4*ty);
            float4 ka4 = *(const float4*)(KsT + w*64  + 4*tx);
            float4 pk0 = *(const float4*)(PKT + w*192 + dkb);
            float4 pk1 = *(const float4*)(PKT + w*192 + dkb + 4);
            float4 pq0 = *(const float4*)(PQT + w*192 + dkb);
            float4 pq1 = *(const float4*)(PQT + w*192 + dkb + 4);
            float q[4]  = {qa4.x, qa4.y, qa4.z, qa4.w};
            float k[4]  = {ka4.x, ka4.y, ka4.z, ka4.w};
            float pk[8] = {pk0.x, pk0.y, pk0.z, pk0.w, pk1.x, pk1.y, pk1.z, pk1.w};
            float pq[8] = {pq0.x, pq0.y, pq0.z, pq0.w, pq1.x, pq1.y, pq1.z, pq1.w};
            #pragma unroll
            for (int ri = 0; ri < 4; ri++)
                #pragma unroll
                for (int rj = 0; rj < 4; rj++) {
                    const int d = ri - rj + 3;
                    s[ri][rj] += q[ri]*k[rj] + q[ri]*pk[d] + k[rj]*pq[d];
                }
        }
        #pragma unroll
        for (int ri = 0; ri < 4; ri++)
            #pragma unroll
            for (int rj = 0; rj < 4; rj++)
                s[ri][rj] *= scale;

        __syncthreads();

        #pragma unroll
        for (int ri = 0; ri < 4; ri++) {
            float mx = fmaxf(fmaxf(s[ri][0], s[ri][1]), fmaxf(s[ri][2], s[ri][3]));
            #pragma unroll
            for (int off = 8; off > 0; off >>= 1)
                mx = fmaxf(mx, __shfl_xor_sync(0xffffffffu, mx, off));
            float mnew = fmaxf(m_i[ri], mx);
            float corr = __expf(m_i[ri] - mnew);
            float p0 = __expf(s[ri][0] - mnew);
            float p1 = __expf(s[ri][1] - mnew);
            float p2 = __expf(s[ri][2] - mnew);
            float p3 = __expf(s[ri][3] - mnew);
            float rs = p0 + p1 + p2 + p3;
            #pragma unroll
            for (int off = 8; off > 0; off >>= 1)
                rs += __shfl_xor_sync(0xffffffffu, rs, off);
            l_i[ri] = l_i[ri]*corr + rs;
            m_i[ri] = mnew;
            #pragma unroll
            for (int rw = 0; rw < 4; rw++) o[ri][rw] *= corr;
            float4 pv = {p0, p1, p2, p3};
            *(float4*)(Ps + (4*ty + ri)*68 + 4*tx) = pv;
        }
        __syncthreads();

        #pragma unroll 4
        for (int j = 0; j < 64; j++) {
            float4 vv = *(const float4*)(Vs + j*64 + 4*tx);
            float va[4] = {vv.x, vv.y, vv.z, vv.w};
            float pa[4];
            #pragma unroll
            for (int ri = 0; ri < 4; ri++) pa[ri] = Ps[(4*ty + ri)*68 + j];
            #pragma unroll
            for (int ri = 0; ri < 4; ri++)
                #pragma unroll
                for (int rw = 0; rw < 4; rw++)
                    o[ri][rw] += pa[ri] * va[rw];
        }
    }

    #pragma unroll
    for (int ri = 0; ri < 4; ri++) {
        int i = i0 + 4*ty + ri;
        float inv = 1.0f / l_i[ri];
        float4 ov = { o[ri][0]*inv, o[ri][1]*inv, o[ri][2]*inv, o[ri][3]*inv };
        *(float4*)(out + ((size_t)b*SLEN + i)*DD + h*64 + 4*tx) = ov;
    }
}

// ===========================================================================
// Launch
// ===========================================================================
extern "C" void kernel_launch(void* const* d_in, const int* in_sizes, int n_in,
                              void* d_out, int out_size)
{
    (void)in_sizes; (void)n_in; (void)out_size;
    const float* x  = (const float*)d_in[0];
    const float* re = (const float*)d_in[1];
    const float* Wq = (const float*)d_in[2];
    const float* bq = (const float*)d_in[3];
    const float* Wk = (const float*)d_in[4];
    const float* bk = (const float*)d_in[5];
    const float* Wv = (const float*)d_in[6];
    const float* bv = (const float*)d_in[7];
    float* out = (float*)d_out;

    void *qp, *kp, *vp, *pkp, *pqp;
    cudaGetSymbolAddress(&qp,  g_Q);
    cudaGetSymbolAddress(&kp,  g_K);
    cudaGetSymbolAddress(&vp,  g_V);
    cudaGetSymbolAddress(&pkp, g_PK);
    cudaGetSymbolAddress(&pqp, g_PQ);

    cudaFuncSetAttribute(proj_mma_kernel, cudaFuncAttributeMaxDynamicSharedMemorySize,
                         P_SMEM_BYTES);
    cudaFuncSetAttribute(attn_kernel, cudaFuncAttributeMaxDynamicSharedMemorySize,
                         ATTN_SMEM_BYTES);

    proj_mma_kernel<<<dim3(40, 24), dim3(256), P_SMEM_BYTES>>>(
        x, re, Wq, bq, Wk, bk, Wv, bv,
        (float*)qp, (float*)kp, (float*)vp, (float*)pkp, (float*)pqp);

    attn_kernel<<<dim3(4, BB, HH), dim3(512), ATTN_SMEM_BYTES>>>(out);
}